// round 15
// baseline (speedup 1.0000x reference)
#include <cuda_runtime.h>
#include <cuda_bf16.h>
#include <cstdint>

#define BB 16384
#define DD 64
#define LCAT 8
#define LTXT 64
#define NTOPIN 79
#define NT1 128
#define NT2 64
#define MTILE 64

#define TOPP_BLOCKS 48
#define PREP_BLOCKS 8
#define FEAT_BLOCKS 1024          // 16 samples each
#define NTILES      (BB / MTILE)  // 256
#define GRID_TOTAL  (TOPP_BLOCKS + PREP_BLOCKS + FEAT_BLOCKS)

typedef unsigned long long u64;

// Packed bf16 hi/lo x, transposed: g_xP[k][s], k in [0,80), zero-padded k=79
__device__ uint32_t g_xP[80 * BB];
// Pre-split weights (K-major rows: [j][k])
__device__ __align__(16) __nv_bfloat16 gW1hi[128 * 80];
__device__ __align__(16) __nv_bfloat16 gW1lo[128 * 80];
__device__ __align__(16) __nv_bfloat16 gW2hi[64 * 128];
__device__ __align__(16) __nv_bfloat16 gW2lo[64 * 128];
// sync: [0..255] per-tile feat counters (target 4), [256] prepack counter
__device__ int g_sync[257];

__device__ __forceinline__ uint32_t smem_u32(const void* p) {
    uint32_t a;
    asm("{ .reg .u64 t; cvta.to.shared.u64 t, %1; cvt.u32.u64 %0, t; }"
        : "=r"(a) : "l"(p));
    return a;
}
__device__ __forceinline__ void ldsm_x4(uint32_t addr, uint32_t* r) {
    asm volatile("ldmatrix.sync.aligned.m8n8.x4.shared.b16 {%0,%1,%2,%3}, [%4];"
        : "=r"(r[0]), "=r"(r[1]), "=r"(r[2]), "=r"(r[3]) : "r"(addr));
}
__device__ __forceinline__ void mma_bf16(float* d, const uint32_t* a,
                                         uint32_t b0, uint32_t b1) {
    asm volatile("mma.sync.aligned.m16n8k16.row.col.f32.bf16.bf16.f32 "
        "{%0,%1,%2,%3}, {%4,%5,%6,%7}, {%8,%9}, {%0,%1,%2,%3};"
        : "+f"(d[0]), "+f"(d[1]), "+f"(d[2]), "+f"(d[3])
        : "r"(a[0]), "r"(a[1]), "r"(a[2]), "r"(a[3]), "r"(b0), "r"(b1));
}
__device__ __forceinline__ void bsplit(float v, __nv_bfloat16& h, __nv_bfloat16& l) {
    h = __float2bfloat16(v);
    l = __float2bfloat16(v - __bfloat162float(h));
}
__device__ __forceinline__ void bsplit2(float v0, float v1,
                                        __nv_bfloat162& ph, __nv_bfloat162& pl) {
    __nv_bfloat16 h0, l0, h1, l1;
    bsplit(v0, h0, l0); bsplit(v1, h1, l1);
    ph.x = h0; ph.y = h1; pl.x = l0; pl.y = l1;
}
__device__ __forceinline__ uint32_t packv(float v) {
    __nv_bfloat16 h, l;
    bsplit(v, h, l);
    return ((uint32_t)__bfloat16_as_ushort(l) << 16) | __bfloat16_as_ushort(h);
}

// ---------------------------------------------------------------------------
// Smem layout for top role
// ---------------------------------------------------------------------------
#define ASTR   272
#define B1STR  176
#define W2STR  272

#define OFF_AHI   0
#define OFF_ALO   (OFF_AHI + MTILE * ASTR)
#define OFF_R2    (OFF_ALO + MTILE * ASTR)
#define OFF_B1HI  (OFF_R2)
#define OFF_B1LO  (OFF_B1HI + 128 * B1STR)
#define OFF_R2END (OFF_B1LO + 128 * B1STR)
#define OFF_W2HI  (OFF_R2)
#define OFF_W2LO  (OFF_W2HI + 64 * W2STR)
#define OFF_SB1   (OFF_R2END)
#define OFF_SB2   (OFF_SB1 + 512)
#define OFF_SW3   (OFF_SB2 + 256)
#define OFF_SB3   (OFF_SW3 + 256)
#define OFF_SPZ   (OFF_SB3 + 16)
#define TOP_SMEM  (OFF_SPZ + 4 * 64 * 4)

// ---------------------------------------------------------------------------
// ONE kernel, three roles by blockIdx.x:
//  [0, TOPP_BLOCKS): PERSISTENT top-MLP blocks, resident from wave 1.
//  [TOPP_BLOCKS, +PREP_BLOCKS): weight split (fast, early).
//  [.., GRID_TOTAL): gather/feature blocks (16 warps = 16 samples each).
// ---------------------------------------------------------------------------
__global__ __launch_bounds__(512, 2) void dlrm_kernel(
    const int* __restrict__ user, const int* __restrict__ item,
    const int* __restrict__ brand, const int* __restrict__ cat_idx,
    const int* __restrict__ cat_len, const int* __restrict__ text_idx,
    const int* __restrict__ text_len, const float* __restrict__ sales_rank,
    const float* __restrict__ user_tab, const float* __restrict__ item_tab,
    const float* __restrict__ brand_tab, const float* __restrict__ cat_tab,
    const float* __restrict__ text_tab,
    const float* __restrict__ W_bot, const float* __restrict__ b_bot,
    const float* __restrict__ W_proj, const float* __restrict__ b_proj,
    const float* __restrict__ W1, const float* __restrict__ b1,
    const float* __restrict__ W2, const float* __restrict__ b2,
    const float* __restrict__ W3, const float* __restrict__ b3,
    float* __restrict__ out)
{
    const unsigned FULL = 0xFFFFFFFFu;
    const int tid = threadIdx.x;
    const int wid = tid >> 5;
    const int lane = tid & 31;

    // ================= role: prepack =================
    if (blockIdx.x >= TOPP_BLOCKS && blockIdx.x < TOPP_BLOCKS + PREP_BLOCKS) {
        int t = (blockIdx.x - TOPP_BLOCKS) * 512 + tid;   // [0, 4096)
        for (int idx = t; idx < 128 * 80; idx += 4096) {
            int j = idx / 80, k = idx % 80;
            float v = (k < NTOPIN) ? W1[k * 128 + j] : 0.f;
            __nv_bfloat16 h, l; bsplit(v, h, l);
            gW1hi[idx] = h; gW1lo[idx] = l;
        }
        for (int idx = t; idx < 64 * 128; idx += 4096) {
            int m = idx >> 7, k = idx & 127;
            float v = W2[k * 64 + m];
            __nv_bfloat16 h, l; bsplit(v, h, l);
            gW2hi[idx] = h; gW2lo[idx] = l;
        }
        __syncthreads();
        if (tid == 0) {
            __threadfence();
            atomicAdd(&g_sync[256], 1);
        }
        return;
    }

    // ================= role: feat (gather + features) =================
    if (blockIdx.x >= TOPP_BLOCKS + PREP_BLOCKS) {
        const int fb = blockIdx.x - (TOPP_BLOCKS + PREP_BLOCKS);
        const int s = fb * 16 + wid;

        const float2* ut = (const float2*)user_tab;
        const float2* it = (const float2*)item_tab;
        const float2* bt = (const float2*)brand_tab;
        const float4* ct4 = (const float4*)cat_tab;
        const float4* tt4 = (const float4*)text_tab;
        const int sub = lane >> 4;
        const int q   = lane & 15;

        int ui = user[s];
        int ii = item[s];
        int bi = brand[s];
        float2 fu = __ldcs(ut + (size_t)ui * 32 + lane);
        float2 fi = __ldcs(it + (size_t)ii * 32 + lane);
        float2 fb2 = bt[(size_t)bi * 32 + lane];

        int clen = cat_len[s];
        int tlen = text_len[s];
        int creg = (lane < LCAT) ? cat_idx[s * LCAT + lane] : 0;
        int t0 = text_idx[s * LTXT + lane];
        int t1 = text_idx[s * LTXT + 32 + lane];

        float4 cacc = make_float4(0.f, 0.f, 0.f, 0.f);
        #pragma unroll
        for (int i = 0; i < LCAT; i += 2) {
            int r = i + sub;
            int idx = __shfl_sync(FULL, creg, r);
            if (r < clen) {
                float4 v = ct4[(size_t)idx * 16 + q];
                cacc.x += v.x; cacc.y += v.y; cacc.z += v.z; cacc.w += v.w;
            }
        }

        float4 tacc = make_float4(0.f, 0.f, 0.f, 0.f);
        #pragma unroll
        for (int g = 0; g < 4; g++) {
            float4 v[8];
            #pragma unroll
            for (int j = 0; j < 8; j++) {
                int i = g * 16 + 2 * j;
                int r = i + sub;
                int idx = __shfl_sync(FULL, (i < 32) ? t0 : t1, r & 31);
                v[j] = make_float4(0.f, 0.f, 0.f, 0.f);
                if (r < tlen) v[j] = __ldcs(tt4 + (size_t)idx * 16 + q);
            }
            float4 p0, p1;
            p0.x = v[0].x + v[1].x; p0.y = v[0].y + v[1].y;
            p0.z = v[0].z + v[1].z; p0.w = v[0].w + v[1].w;
            p1.x = v[2].x + v[3].x; p1.y = v[2].y + v[3].y;
            p1.z = v[2].z + v[3].z; p1.w = v[2].w + v[3].w;
            p0.x += v[4].x + v[5].x; p0.y += v[4].y + v[5].y;
            p0.z += v[4].z + v[5].z; p0.w += v[4].w + v[5].w;
            p1.x += v[6].x + v[7].x; p1.y += v[6].y + v[7].y;
            p1.z += v[6].z + v[7].z; p1.w += v[6].w + v[7].w;
            tacc.x += p0.x + p1.x; tacc.y += p0.y + p1.y;
            tacc.z += p0.z + p1.z; tacc.w += p0.w + p1.w;
        }

        {
            float cinv = 1.f / (float)max(clen, 1);
            float tinv = 1.f / (float)max(tlen, 1);
            cacc.x = (cacc.x + __shfl_down_sync(FULL, cacc.x, 16)) * cinv;
            cacc.y = (cacc.y + __shfl_down_sync(FULL, cacc.y, 16)) * cinv;
            cacc.z = (cacc.z + __shfl_down_sync(FULL, cacc.z, 16)) * cinv;
            cacc.w = (cacc.w + __shfl_down_sync(FULL, cacc.w, 16)) * cinv;
            tacc.x = (tacc.x + __shfl_down_sync(FULL, tacc.x, 16)) * tinv;
            tacc.y = (tacc.y + __shfl_down_sync(FULL, tacc.y, 16)) * tinv;
            tacc.z = (tacc.z + __shfl_down_sync(FULL, tacc.z, 16)) * tinv;
            tacc.w = (tacc.w + __shfl_down_sync(FULL, tacc.w, 16)) * tinv;
        }

        float2 cv, tv;
        {
            int src = lane >> 1;
            float cx = __shfl_sync(FULL, cacc.x, src);
            float cy = __shfl_sync(FULL, cacc.y, src);
            float cz = __shfl_sync(FULL, cacc.z, src);
            float cw = __shfl_sync(FULL, cacc.w, src);
            float tx = __shfl_sync(FULL, tacc.x, src);
            float ty = __shfl_sync(FULL, tacc.y, src);
            float tz = __shfl_sync(FULL, tacc.z, src);
            float tw = __shfl_sync(FULL, tacc.w, src);
            if (lane & 1) { cv = make_float2(cz, cw); tv = make_float2(tz, tw); }
            else          { cv = make_float2(cx, cy); tv = make_float2(tx, ty); }
        }

        float sr = sales_rank[s];
        float d0 = fmaxf(fmaf(sr, W_bot[2 * lane],     b_bot[2 * lane]),     0.f);
        float d1 = fmaxf(fmaf(sr, W_bot[2 * lane + 1], b_bot[2 * lane + 1]), 0.f);

        const float2* wp = (const float2*)W_proj;
        float2 du = make_float2(b_proj[2 * lane], b_proj[2 * lane + 1]);
        #pragma unroll
        for (int k = 0; k < DD; k++) {
            float dk = __shfl_sync(FULL, (k & 1) ? d1 : d0, k >> 1);
            float2 w = wp[k * 32 + lane];
            du.x = fmaf(dk, w.x, du.x);
            du.y = fmaf(dk, w.y, du.y);
        }

        float2 f[6];
        f[0] = fu; f[1] = fi; f[2] = fb2; f[3] = cv; f[4] = tv; f[5] = du;

        float keep = 0.f;
        int p = 0;
        #pragma unroll
        for (int a = 0; a < 6; a++) {
            #pragma unroll
            for (int b = a + 1; b < 6; b++) {
                float dv = f[a].x * f[b].x + f[a].y * f[b].y;
                #pragma unroll
                for (int o = 16; o > 0; o >>= 1)
                    dv += __shfl_xor_sync(FULL, dv, o);
                if (lane == p) keep = dv;
                p++;
            }
        }

        if (lane < 15) g_xP[lane * BB + s] = packv(keep);
        g_xP[(15 + 2 * lane) * BB + s] = packv(d0);
        g_xP[(16 + 2 * lane) * BB + s] = packv(d1);
        if (lane == 31) g_xP[79 * BB + s] = 0u;

        __syncthreads();
        if (tid == 0) {
            __threadfence();
            atomicAdd(&g_sync[fb >> 2], 1);   // 4 feat blocks per 64-tile
        }
        return;
    }

    // ================= role: PERSISTENT top MLP =================
    extern __shared__ __align__(16) char sm[];
    const uint32_t smb = smem_u32(sm);

    float* sb1 = (float*)(sm + OFF_SB1);
    float* sb2 = (float*)(sm + OFF_SB2);
    float* sW3 = (float*)(sm + OFF_SW3);
    float* sb3 = (float*)(sm + OFF_SB3);
    float* sPz = (float*)(sm + OFF_SPZ);

    // biases once
    if (tid < 128) sb1[tid] = b1[tid];
    if (tid < 64) { sb2[tid] = b2[tid]; sW3[tid] = W3[tid]; }
    if (tid == 0) sb3[0] = b3[0];

    // wait for prepack once
    if (tid == 0) {
        volatile int* vs = g_sync;
        while (vs[256] < PREP_BLOCKS) { __nanosleep(256); }
        __threadfence();
    }

    const int mt  = wid >> 2;
    const int ntb = (wid & 3) * 32;
    const uint32_t a_lane_off = (mt * 16 + (lane & 15)) * ASTR + ((lane >> 4) * 8) * 2;
    const uint32_t b_row = (lane & 7) + ((lane >> 4) & 1) * 8;
    const uint32_t b_k8  = ((lane >> 3) & 1) * 8;
    const int n0 = (wid & 3) * 16;

    for (int tile = blockIdx.x; tile < NTILES; tile += TOPP_BLOCKS) {
        const int S0 = tile * MTILE;

        // wait for this tile's 4 feat blocks
        if (tid == 0) {
            volatile int* vs = g_sync;
            while (vs[tile] < 4) { __nanosleep(128); }
            __threadfence();
        }
        __syncthreads();   // also guards smem reuse from previous tile

        // stage A from packed xP + restage B1 (W2 overlay clobbered it)
        #pragma unroll
        for (int it = 0; it < 5; it++) {
            int idx = tid + it * 512;
            int row = idx & 63, k0 = (idx >> 6) * 2;
            uint32_t p0 = g_xP[(size_t)k0 * BB + S0 + row];
            uint32_t p1 = g_xP[(size_t)(k0 + 1) * BB + S0 + row];
            uint32_t hp = __byte_perm(p0, p1, 0x5410);
            uint32_t lp = __byte_perm(p0, p1, 0x7632);
            *(uint32_t*)(sm + OFF_AHI + row * ASTR + k0 * 2) = hp;
            *(uint32_t*)(sm + OFF_ALO + row * ASTR + k0 * 2) = lp;
        }
        for (int idx = tid; idx < 1280; idx += 512) {
            int r = idx / 10, c = idx % 10;
            *(uint4*)(sm + OFF_B1HI + r * B1STR + c * 16) =
                *(const uint4*)(gW1hi + r * 80 + c * 8);
            *(uint4*)(sm + OFF_B1LO + r * B1STR + c * 16) =
                *(const uint4*)(gW1lo + r * 80 + c * 8);
        }
        __syncthreads();

        // layer 1
        float acc[4][4];
        #pragma unroll
        for (int i = 0; i < 4; i++)
            #pragma unroll
            for (int j = 0; j < 4; j++) acc[i][j] = 0.f;

        #pragma unroll
        for (int term = 0; term < 3; term++) {
            uint32_t abase = smb + ((term == 2) ? OFF_ALO : OFF_AHI);
            uint32_t bbase = smb + ((term == 1) ? OFF_B1LO : OFF_B1HI);
            #pragma unroll
            for (int ks = 0; ks < 5; ks++) {
                int k0 = ks * 16;
                uint32_t af[4];
                ldsm_x4(abase + a_lane_off + k0 * 2, af);
                #pragma unroll
                for (int half = 0; half < 2; half++) {
                    uint32_t bf[4];
                    int nn = ntb + half * 16;
                    ldsm_x4(bbase + (nn + b_row) * B1STR + (k0 + b_k8) * 2, bf);
                    mma_bf16(acc[half * 2],     af, bf[0], bf[1]);
                    mma_bf16(acc[half * 2 + 1], af, bf[2], bf[3]);
                }
            }
        }
        __syncthreads();

        // epilogue 1: h1 -> A region; W2 overlay
        {
            int r0 = mt * 16 + (lane >> 2);
            #pragma unroll
            for (int nt = 0; nt < 4; nt++) {
                int c = ntb + nt * 8 + 2 * (lane & 3);
                float h0a = fmaxf(acc[nt][0] + sb1[c],     0.f);
                float h1a = fmaxf(acc[nt][1] + sb1[c + 1], 0.f);
                float h0b = fmaxf(acc[nt][2] + sb1[c],     0.f);
                float h1b = fmaxf(acc[nt][3] + sb1[c + 1], 0.f);
                __nv_bfloat162 ph, pl;
                bsplit2(h0a, h1a, ph, pl);
                *(__nv_bfloat162*)(sm + OFF_AHI + r0 * ASTR + c * 2) = ph;
                *(__nv_bfloat162*)(sm + OFF_ALO + r0 * ASTR + c * 2) = pl;
                bsplit2(h0b, h1b, ph, pl);
                *(__nv_bfloat162*)(sm + OFF_AHI + (r0 + 8) * ASTR + c * 2) = ph;
                *(__nv_bfloat162*)(sm + OFF_ALO + (r0 + 8) * ASTR + c * 2) = pl;
            }
        }
        {
            #pragma unroll
            for (int it = 0; it < 2; it++) {
                int idx = tid + it * 512;
                int r = idx >> 4, c = idx & 15;
                *(uint4*)(sm + OFF_W2HI + r * W2STR + c * 16) =
                    *(const uint4*)(gW2hi + r * 128 + c * 8);
                *(uint4*)(sm + OFF_W2LO + r * W2STR + c * 16) =
                    *(const uint4*)(gW2lo + r * 128 + c * 8);
            }
        }
        __syncthreads();

        // layer 2
        float acc2[2][4];
        #pragma unroll
        for (int i = 0; i < 2; i++)
            #pragma unroll
            for (int j = 0; j < 4; j++) acc2[i][j] = 0.f;

        #pragma unroll
        for (int term = 0; term < 3; term++) {
            uint32_t abase = smb + ((term == 2) ? OFF_ALO : OFF_AHI);
            uint32_t bbase = smb + ((term == 1) ? OFF_W2LO : OFF_W2HI);
            #pragma unroll
            for (int ks = 0; ks < 8; ks++) {
                int k0 = ks * 16;
                uint32_t af[4];
                ldsm_x4(abase + a_lane_off + k0 * 2, af);
                uint32_t bf[4];
                ldsm_x4(bbase + (n0 + b_row) * W2STR + (k0 + b_k8) * 2, bf);
                mma_bf16(acc2[0], af, bf[0], bf[1]);
                mma_bf16(acc2[1], af, bf[2], bf[3]);
            }
        }

        // layer-3 partials + reduction
        {
            float z0 = 0.f, z1 = 0.f;
            #pragma unroll
            for (int nt = 0; nt < 2; nt++) {
                int c = n0 + nt * 8 + 2 * (lane & 3);
                float w0 = sW3[c], w1 = sW3[c + 1];
                z0 = fmaf(fmaxf(acc2[nt][0] + sb2[c],     0.f), w0, z0);
                z0 = fmaf(fmaxf(acc2[nt][1] + sb2[c + 1], 0.f), w1, z0);
                z1 = fmaf(fmaxf(acc2[nt][2] + sb2[c],     0.f), w0, z1);
                z1 = fmaf(fmaxf(acc2[nt][3] + sb2[c + 1], 0.f), w1, z1);
            }
            z0 += __shfl_xor_sync(FULL, z0, 1);
            z0 += __shfl_xor_sync(FULL, z0, 2);
            z1 += __shfl_xor_sync(FULL, z1, 1);
            z1 += __shfl_xor_sync(FULL, z1, 2);
            if ((lane & 3) == 0) {
                int r0 = mt * 16 + (lane >> 2);
                int ng = wid & 3;
                sPz[ng * 64 + r0]     = z0;
                sPz[ng * 64 + r0 + 8] = z1;
            }
        }
        __syncthreads();

        if (tid < 64) {
            float z = sb3[0] + sPz[tid] + sPz[64 + tid] + sPz[128 + tid] + sPz[192 + tid];
            out[S0 + tid] = 1.f / (1.f + __expf(-z));
        }
    }
}

// ---------------------------------------------------------------------------
extern "C" void kernel_launch(void* const* d_in, const int* in_sizes, int n_in,
                              void* d_out, int out_size)
{
    const int*   user       = (const int*)  d_in[0];
    const int*   item       = (const int*)  d_in[1];
    const int*   brand_idx  = (const int*)  d_in[2];
    const int*   cat_idx    = (const int*)  d_in[3];
    const int*   cat_len    = (const int*)  d_in[4];
    const int*   text_idx   = (const int*)  d_in[5];
    const int*   text_len   = (const int*)  d_in[6];
    const float* sales_rank = (const float*)d_in[7];
    const float* user_tab   = (const float*)d_in[8];
    const float* item_tab   = (const float*)d_in[9];
    const float* brand_tab  = (const float*)d_in[10];
    const float* cat_tab    = (const float*)d_in[11];
    const float* text_tab   = (const float*)d_in[12];
    const float* W_bot      = (const float*)d_in[13];
    const float* b_bot      = (const float*)d_in[14];
    const float* W_proj     = (const float*)d_in[15];
    const float* b_proj     = (const float*)d_in[16];
    const float* W_t1       = (const float*)d_in[17];
    const float* b_t1       = (const float*)d_in[18];
    const float* W_t2       = (const float*)d_in[19];
    const float* b_t2       = (const float*)d_in[20];
    const float* W_t3       = (const float*)d_in[21];
    const float* b_t3       = (const float*)d_in[22];
    float* out = (float*)d_out;

    cudaFuncSetAttribute(dlrm_kernel,
                         cudaFuncAttributeMaxDynamicSharedMemorySize,
                         TOP_SMEM);

    // zero the sync counters each call (graph-capturable memset node)
    static void* sync_addr = nullptr;
    if (!sync_addr) cudaGetSymbolAddress(&sync_addr, g_sync);
    cudaMemsetAsync(sync_addr, 0, 257 * sizeof(int), 0);

    dlrm_kernel<<<GRID_TOTAL, 512, TOP_SMEM>>>(
        user, item, brand_idx, cat_idx, cat_len, text_idx, text_len,
        sales_rank, user_tab, item_tab, brand_tab, cat_tab, text_tab,
        W_bot, b_bot, W_proj, b_proj,
        W_t1, b_t1, W_t2, b_t2, W_t3, b_t3, out);
}

// round 16
// speedup vs baseline: 1.4086x; 1.4086x over previous
#include <cuda_runtime.h>
#include <cuda_bf16.h>
#include <cstdint>

#define BB 16384
#define DD 64
#define LCAT 8
#define LTXT 64
#define NTOPIN 79
#define NT1 128
#define NT2 64
#define SAMP_BLOCKS (BB / 8)
#define MTILE 64

typedef unsigned long long u64;

// Packed bf16 hi/lo x, transposed: g_xP[k][s], k in [0,80), zero-padded k=79
__device__ uint32_t g_xP[80 * BB];
// Pre-split weights (K-major rows: [j][k])
__device__ __align__(16) __nv_bfloat16 gW1hi[128 * 80];
__device__ __align__(16) __nv_bfloat16 gW1lo[128 * 80];
__device__ __align__(16) __nv_bfloat16 gW2hi[64 * 128];
__device__ __align__(16) __nv_bfloat16 gW2lo[64 * 128];

__device__ __forceinline__ uint32_t smem_u32(const void* p) {
    uint32_t a;
    asm("{ .reg .u64 t; cvta.to.shared.u64 t, %1; cvt.u32.u64 %0, t; }"
        : "=r"(a) : "l"(p));
    return a;
}
__device__ __forceinline__ void ldsm_x4(uint32_t addr, uint32_t* r) {
    asm volatile("ldmatrix.sync.aligned.m8n8.x4.shared.b16 {%0,%1,%2,%3}, [%4];"
        : "=r"(r[0]), "=r"(r[1]), "=r"(r[2]), "=r"(r[3]) : "r"(addr));
}
__device__ __forceinline__ void mma_bf16(float* d, const uint32_t* a,
                                         uint32_t b0, uint32_t b1) {
    asm volatile("mma.sync.aligned.m16n8k16.row.col.f32.bf16.bf16.f32 "
        "{%0,%1,%2,%3}, {%4,%5,%6,%7}, {%8,%9}, {%0,%1,%2,%3};"
        : "+f"(d[0]), "+f"(d[1]), "+f"(d[2]), "+f"(d[3])
        : "r"(a[0]), "r"(a[1]), "r"(a[2]), "r"(a[3]), "r"(b0), "r"(b1));
}
__device__ __forceinline__ void bsplit(float v, __nv_bfloat16& h, __nv_bfloat16& l) {
    h = __float2bfloat16(v);
    l = __float2bfloat16(v - __bfloat162float(h));
}
__device__ __forceinline__ void bsplit2(float v0, float v1,
                                        __nv_bfloat162& ph, __nv_bfloat162& pl) {
    __nv_bfloat16 h0, l0, h1, l1;
    bsplit(v0, h0, l0); bsplit(v1, h1, l1);
    ph.x = h0; ph.y = h1; pl.x = l0; pl.y = l1;
}
__device__ __forceinline__ uint32_t packv(float v) {
    __nv_bfloat16 h, l;
    bsplit(v, h, l);
    return ((uint32_t)__bfloat16_as_ushort(l) << 16) | __bfloat16_as_ushort(h);
}

// ---------------------------------------------------------------------------
// Kernel 1: warp-per-sample + embedded weight prepack (8 trailing blocks).
// IDENTICAL to R12 (best measured feat: ~34.5us).
// ---------------------------------------------------------------------------
__global__ __launch_bounds__(256, 4) void feat_kernel(
    const int* __restrict__ user, const int* __restrict__ item,
    const int* __restrict__ brand, const int* __restrict__ cat_idx,
    const int* __restrict__ cat_len, const int* __restrict__ text_idx,
    const int* __restrict__ text_len, const float* __restrict__ sales_rank,
    const float* __restrict__ user_tab, const float* __restrict__ item_tab,
    const float* __restrict__ brand_tab, const float* __restrict__ cat_tab,
    const float* __restrict__ text_tab,
    const float* __restrict__ W_bot, const float* __restrict__ b_bot,
    const float* __restrict__ W_proj, const float* __restrict__ b_proj,
    const float* __restrict__ W1,    const float* __restrict__ W2)
{
    const unsigned FULL = 0xFFFFFFFFu;

    if (blockIdx.x >= SAMP_BLOCKS) {
        int tid = (blockIdx.x - SAMP_BLOCKS) * 256 + threadIdx.x;
        for (int idx = tid; idx < 128 * 80; idx += 2048) {
            int j = idx / 80, k = idx % 80;
            float v = (k < NTOPIN) ? W1[k * 128 + j] : 0.f;
            __nv_bfloat16 h, l; bsplit(v, h, l);
            gW1hi[idx] = h; gW1lo[idx] = l;
        }
        for (int idx = tid; idx < 64 * 128; idx += 2048) {
            int m = idx >> 7, k = idx & 127;
            float v = W2[k * 64 + m];
            __nv_bfloat16 h, l; bsplit(v, h, l);
            gW2hi[idx] = h; gW2lo[idx] = l;
        }
        return;
    }

    int gwarp = (blockIdx.x * blockDim.x + threadIdx.x) >> 5;
    int lane  = threadIdx.x & 31;
    const int s = gwarp;

    const float2* ut = (const float2*)user_tab;
    const float2* it = (const float2*)item_tab;
    const float2* bt = (const float2*)brand_tab;
    const float4* ct4 = (const float4*)cat_tab;
    const float4* tt4 = (const float4*)text_tab;

    const int sub = lane >> 4;
    const int q   = lane & 15;

    int ui = user[s];
    int ii = item[s];
    int bi = brand[s];
    float2 fu = __ldcs(ut + (size_t)ui * 32 + lane);
    float2 fi = __ldcs(it + (size_t)ii * 32 + lane);
    float2 fb = bt[(size_t)bi * 32 + lane];

    int clen = cat_len[s];
    int tlen = text_len[s];
    int creg = (lane < LCAT) ? cat_idx[s * LCAT + lane] : 0;
    int t0 = text_idx[s * LTXT + lane];
    int t1 = text_idx[s * LTXT + 32 + lane];

    float4 cacc = make_float4(0.f, 0.f, 0.f, 0.f);
    #pragma unroll
    for (int i = 0; i < LCAT; i += 2) {
        int r = i + sub;
        int idx = __shfl_sync(FULL, creg, r);
        if (r < clen) {
            float4 v = ct4[(size_t)idx * 16 + q];
            cacc.x += v.x; cacc.y += v.y; cacc.z += v.z; cacc.w += v.w;
        }
    }

    float4 tacc = make_float4(0.f, 0.f, 0.f, 0.f);
    #pragma unroll
    for (int g = 0; g < 4; g++) {
        float4 v[8];
        #pragma unroll
        for (int j = 0; j < 8; j++) {
            int i = g * 16 + 2 * j;
            int r = i + sub;
            int idx = __shfl_sync(FULL, (i < 32) ? t0 : t1, r & 31);
            v[j] = make_float4(0.f, 0.f, 0.f, 0.f);
            if (r < tlen) v[j] = __ldcs(tt4 + (size_t)idx * 16 + q);
        }
        float4 p0, p1;
        p0.x = v[0].x + v[1].x; p0.y = v[0].y + v[1].y;
        p0.z = v[0].z + v[1].z; p0.w = v[0].w + v[1].w;
        p1.x = v[2].x + v[3].x; p1.y = v[2].y + v[3].y;
        p1.z = v[2].z + v[3].z; p1.w = v[2].w + v[3].w;
        p0.x += v[4].x + v[5].x; p0.y += v[4].y + v[5].y;
        p0.z += v[4].z + v[5].z; p0.w += v[4].w + v[5].w;
        p1.x += v[6].x + v[7].x; p1.y += v[6].y + v[7].y;
        p1.z += v[6].z + v[7].z; p1.w += v[6].w + v[7].w;
        tacc.x += p0.x + p1.x; tacc.y += p0.y + p1.y;
        tacc.z += p0.z + p1.z; tacc.w += p0.w + p1.w;
    }

    {
        float cinv = 1.f / (float)max(clen, 1);
        float tinv = 1.f / (float)max(tlen, 1);
        cacc.x = (cacc.x + __shfl_down_sync(FULL, cacc.x, 16)) * cinv;
        cacc.y = (cacc.y + __shfl_down_sync(FULL, cacc.y, 16)) * cinv;
        cacc.z = (cacc.z + __shfl_down_sync(FULL, cacc.z, 16)) * cinv;
        cacc.w = (cacc.w + __shfl_down_sync(FULL, cacc.w, 16)) * cinv;
        tacc.x = (tacc.x + __shfl_down_sync(FULL, tacc.x, 16)) * tinv;
        tacc.y = (tacc.y + __shfl_down_sync(FULL, tacc.y, 16)) * tinv;
        tacc.z = (tacc.z + __shfl_down_sync(FULL, tacc.z, 16)) * tinv;
        tacc.w = (tacc.w + __shfl_down_sync(FULL, tacc.w, 16)) * tinv;
    }

    float2 cv, tv;
    {
        int src = lane >> 1;
        float cx = __shfl_sync(FULL, cacc.x, src);
        float cy = __shfl_sync(FULL, cacc.y, src);
        float cz = __shfl_sync(FULL, cacc.z, src);
        float cw = __shfl_sync(FULL, cacc.w, src);
        float tx = __shfl_sync(FULL, tacc.x, src);
        float ty = __shfl_sync(FULL, tacc.y, src);
        float tz = __shfl_sync(FULL, tacc.z, src);
        float tw = __shfl_sync(FULL, tacc.w, src);
        if (lane & 1) { cv = make_float2(cz, cw); tv = make_float2(tz, tw); }
        else          { cv = make_float2(cx, cy); tv = make_float2(tx, ty); }
    }

    float sr = sales_rank[s];
    float d0 = fmaxf(fmaf(sr, W_bot[2 * lane],     b_bot[2 * lane]),     0.f);
    float d1 = fmaxf(fmaf(sr, W_bot[2 * lane + 1], b_bot[2 * lane + 1]), 0.f);

    const float2* wp = (const float2*)W_proj;
    float2 du = make_float2(b_proj[2 * lane], b_proj[2 * lane + 1]);
    #pragma unroll
    for (int k = 0; k < DD; k++) {
        float dk = __shfl_sync(FULL, (k & 1) ? d1 : d0, k >> 1);
        float2 w = wp[k * 32 + lane];
        du.x = fmaf(dk, w.x, du.x);
        du.y = fmaf(dk, w.y, du.y);
    }

    float2 f[6];
    f[0] = fu; f[1] = fi; f[2] = fb; f[3] = cv; f[4] = tv; f[5] = du;

    float keep = 0.f;
    int p = 0;
    #pragma unroll
    for (int a = 0; a < 6; a++) {
        #pragma unroll
        for (int b = a + 1; b < 6; b++) {
            float dv = f[a].x * f[b].x + f[a].y * f[b].y;
            #pragma unroll
            for (int o = 16; o > 0; o >>= 1)
                dv += __shfl_xor_sync(FULL, dv, o);
            if (lane == p) keep = dv;
            p++;
        }
    }

    if (lane < 15) g_xP[lane * BB + s] = packv(keep);
    g_xP[(15 + 2 * lane) * BB + s] = packv(d0);
    g_xP[(16 + 2 * lane) * BB + s] = packv(d1);
    if (lane == 31) g_xP[79 * BB + s] = 0u;
}

// ---------------------------------------------------------------------------
// Kernel 2: top MLP. NEW layout: A gets tight 176B stride; W2 has its OWN
// region (staged up-front with x and W1 in one deep-MLP burst); h1 overlays
// the dead B1 region after the L1 MMA. Same MMA code as R12.
// ---------------------------------------------------------------------------
#define ASTR   176      // x rows: 80 bf16 = 160B
#define H1STR  272      // h1 rows: 128 bf16 = 256B
#define B1STR  176
#define W2STR  272

#define OFF_AHI   0
#define OFF_ALO   (OFF_AHI + MTILE * ASTR)          // 11264
#define OFF_B1HI  (OFF_ALO + MTILE * ASTR)          // 22528
#define OFF_B1LO  (OFF_B1HI + 128 * B1STR)          // 45056
#define OFF_H1HI  OFF_B1HI                          // overlay (64*272=17408 fits)
#define OFF_H1LO  OFF_B1LO
#define OFF_W2HI  (OFF_B1LO + 128 * B1STR)          // 67584
#define OFF_W2LO  (OFF_W2HI + 64 * W2STR)           // 84992
#define OFF_SB1   (OFF_W2LO + 64 * W2STR)           // 102400
#define OFF_SB2   (OFF_SB1 + 512)
#define OFF_SW3   (OFF_SB2 + 256)
#define OFF_SB3   (OFF_SW3 + 256)
#define OFF_SPZ   (OFF_SB3 + 16)
#define TOP_SMEM  (OFF_SPZ + 4 * 64 * 4)            // ~104.5KB -> 2 CTAs/SM

__global__ __launch_bounds__(512, 2) void top_mma(
    const float* __restrict__ b1, const float* __restrict__ b2,
    const float* __restrict__ W3, const float* __restrict__ b3,
    float* __restrict__ out)
{
    extern __shared__ __align__(16) char sm[];
    const uint32_t smb = smem_u32(sm);
    const int tid = threadIdx.x;
    const int wid = tid >> 5;
    const int lane = tid & 31;
    const int S0 = blockIdx.x * MTILE;
    const unsigned FULL = 0xFFFFFFFFu;

    float* sb1 = (float*)(sm + OFF_SB1);
    float* sb2 = (float*)(sm + OFF_SB2);
    float* sW3 = (float*)(sm + OFF_SW3);
    float* sb3 = (float*)(sm + OFF_SB3);
    float* sPz = (float*)(sm + OFF_SPZ);

    // ---- phase 0: ALL global staging up-front (x, W1, W2, biases) ----
    #pragma unroll
    for (int it = 0; it < 5; it++) {
        int idx = tid + it * 512;
        int row = idx & 63, k0 = (idx >> 6) * 2;
        uint32_t p0 = g_xP[(size_t)k0 * BB + S0 + row];
        uint32_t p1 = g_xP[(size_t)(k0 + 1) * BB + S0 + row];
        uint32_t hp = __byte_perm(p0, p1, 0x5410);
        uint32_t lp = __byte_perm(p0, p1, 0x7632);
        *(uint32_t*)(sm + OFF_AHI + row * ASTR + k0 * 2) = hp;
        *(uint32_t*)(sm + OFF_ALO + row * ASTR + k0 * 2) = lp;
    }
    for (int idx = tid; idx < 1280; idx += 512) {
        int r = idx / 10, c = idx % 10;
        *(uint4*)(sm + OFF_B1HI + r * B1STR + c * 16) =
            *(const uint4*)(gW1hi + r * 80 + c * 8);
        *(uint4*)(sm + OFF_B1LO + r * B1STR + c * 16) =
            *(const uint4*)(gW1lo + r * 80 + c * 8);
    }
    #pragma unroll
    for (int it = 0; it < 2; it++) {
        int idx = tid + it * 512;
        int r = idx >> 4, c = idx & 15;
        *(uint4*)(sm + OFF_W2HI + r * W2STR + c * 16) =
            *(const uint4*)(gW2hi + r * 128 + c * 8);
        *(uint4*)(sm + OFF_W2LO + r * W2STR + c * 16) =
            *(const uint4*)(gW2lo + r * 128 + c * 8);
    }
    if (tid < 128) sb1[tid] = b1[tid];
    if (tid < 64) { sb2[tid] = b2[tid]; sW3[tid] = W3[tid]; }
    if (tid == 0) sb3[0] = b3[0];
    __syncthreads();

    // ================= layer 1 (D1 = 64x128) =================
    const int mt  = wid >> 2;
    const int ntb = (wid & 3) * 32;
    float acc[4][4];
    #pragma unroll
    for (int i = 0; i < 4; i++)
        #pragma unroll
        for (int j = 0; j < 4; j++) acc[i][j] = 0.f;

    const uint32_t a1_off = (mt * 16 + (lane & 15)) * ASTR + ((lane >> 4) * 8) * 2;
    const uint32_t a2_off = (mt * 16 + (lane & 15)) * H1STR + ((lane >> 4) * 8) * 2;
    const uint32_t b_row = (lane & 7) + ((lane >> 4) & 1) * 8;
    const uint32_t b_k8  = ((lane >> 3) & 1) * 8;

    #pragma unroll
    for (int term = 0; term < 3; term++) {
        uint32_t abase = smb + ((term == 2) ? OFF_ALO : OFF_AHI);
        uint32_t bbase = smb + ((term == 1) ? OFF_B1LO : OFF_B1HI);
        #pragma unroll
        for (int ks = 0; ks < 5; ks++) {
            int k0 = ks * 16;
            uint32_t af[4];
            ldsm_x4(abase + a1_off + k0 * 2, af);
            #pragma unroll
            for (int half = 0; half < 2; half++) {
                uint32_t bf[4];
                int n0 = ntb + half * 16;
                ldsm_x4(bbase + (n0 + b_row) * B1STR + (k0 + b_k8) * 2, bf);
                mma_bf16(acc[half * 2],     af, bf[0], bf[1]);
                mma_bf16(acc[half * 2 + 1], af, bf[2], bf[3]);
            }
        }
    }
    __syncthreads();   // everyone done reading B1 before h1 overlays it

    // ---- epilogue 1: h1 = relu(D1 + b1) -> H1 region (overlays B1) ----
    {
        int r0 = mt * 16 + (lane >> 2);
        #pragma unroll
        for (int nt = 0; nt < 4; nt++) {
            int c = ntb + nt * 8 + 2 * (lane & 3);
            float h0a = fmaxf(acc[nt][0] + sb1[c],     0.f);
            float h1a = fmaxf(acc[nt][1] + sb1[c + 1], 0.f);
            float h0b = fmaxf(acc[nt][2] + sb1[c],     0.f);
            float h1b = fmaxf(acc[nt][3] + sb1[c + 1], 0.f);
            __nv_bfloat162 ph, pl;
            bsplit2(h0a, h1a, ph, pl);
            *(__nv_bfloat162*)(sm + OFF_H1HI + r0 * H1STR + c * 2) = ph;
            *(__nv_bfloat162*)(sm + OFF_H1LO + r0 * H1STR + c * 2) = pl;
            bsplit2(h0b, h1b, ph, pl);
            *(__nv_bfloat162*)(sm + OFF_H1HI + (r0 + 8) * H1STR + c * 2) = ph;
            *(__nv_bfloat162*)(sm + OFF_H1LO + (r0 + 8) * H1STR + c * 2) = pl;
        }
    }
    __syncthreads();

    // ================= layer 2 (D2 = 64x64) =================
    const int n0 = (wid & 3) * 16;
    float acc2[2][4];
    #pragma unroll
    for (int i = 0; i < 2; i++)
        #pragma unroll
        for (int j = 0; j < 4; j++) acc2[i][j] = 0.f;

    #pragma unroll
    for (int term = 0; term < 3; term++) {
        uint32_t abase = smb + ((term == 2) ? OFF_H1LO : OFF_H1HI);
        uint32_t bbase = smb + ((term == 1) ? OFF_W2LO : OFF_W2HI);
        #pragma unroll
        for (int ks = 0; ks < 8; ks++) {
            int k0 = ks * 16;
            uint32_t af[4];
            ldsm_x4(abase + a2_off + k0 * 2, af);
            uint32_t bf[4];
            ldsm_x4(bbase + (n0 + b_row) * W2STR + (k0 + b_k8) * 2, bf);
            mma_bf16(acc2[0], af, bf[0], bf[1]);
            mma_bf16(acc2[1], af, bf[2], bf[3]);
        }
    }

    // ---- layer-3 partials + reduction + sigmoid ----
    {
        float z0 = 0.f, z1 = 0.f;
        #pragma unroll
        for (int nt = 0; nt < 2; nt++) {
            int c = n0 + nt * 8 + 2 * (lane & 3);
            float w0 = sW3[c], w1 = sW3[c + 1];
            z0 = fmaf(fmaxf(acc2[nt][0] + sb2[c],     0.f), w0, z0);
            z0 = fmaf(fmaxf(acc2[nt][1] + sb2[c + 1], 0.f), w1, z0);
            z1 = fmaf(fmaxf(acc2[nt][2] + sb2[c],     0.f), w0, z1);
            z1 = fmaf(fmaxf(acc2[nt][3] + sb2[c + 1], 0.f), w1, z1);
        }
        z0 += __shfl_xor_sync(FULL, z0, 1);
        z0 += __shfl_xor_sync(FULL, z0, 2);
        z1 += __shfl_xor_sync(FULL, z1, 1);
        z1 += __shfl_xor_sync(FULL, z1, 2);
        if ((lane & 3) == 0) {
            int r0 = mt * 16 + (lane >> 2);
            int ng = wid & 3;
            sPz[ng * 64 + r0]     = z0;
            sPz[ng * 64 + r0 + 8] = z1;
        }
    }
    __syncthreads();

    if (tid < 64) {
        float z = sb3[0] + sPz[tid] + sPz[64 + tid] + sPz[128 + tid] + sPz[192 + tid];
        out[S0 + tid] = 1.f / (1.f + __expf(-z));
    }
}

// ---------------------------------------------------------------------------
extern "C" void kernel_launch(void* const* d_in, const int* in_sizes, int n_in,
                              void* d_out, int out_size)
{
    const int*   user       = (const int*)  d_in[0];
    const int*   item       = (const int*)  d_in[1];
    const int*   brand_idx  = (const int*)  d_in[2];
    const int*   cat_idx    = (const int*)  d_in[3];
    const int*   cat_len    = (const int*)  d_in[4];
    const int*   text_idx   = (const int*)  d_in[5];
    const int*   text_len   = (const int*)  d_in[6];
    const float* sales_rank = (const float*)d_in[7];
    const float* user_tab   = (const float*)d_in[8];
    const float* item_tab   = (const float*)d_in[9];
    const float* brand_tab  = (const float*)d_in[10];
    const float* cat_tab    = (const float*)d_in[11];
    const float* text_tab   = (const float*)d_in[12];
    const float* W_bot      = (const float*)d_in[13];
    const float* b_bot      = (const float*)d_in[14];
    const float* W_proj     = (const float*)d_in[15];
    const float* b_proj     = (const float*)d_in[16];
    const float* W_t1       = (const float*)d_in[17];
    const float* b_t1       = (const float*)d_in[18];
    const float* W_t2       = (const float*)d_in[19];
    const float* b_t2       = (const float*)d_in[20];
    const float* W_t3       = (const float*)d_in[21];
    const float* b_t3       = (const float*)d_in[22];
    float* out = (float*)d_out;

    cudaFuncSetAttribute(top_mma,
                         cudaFuncAttributeMaxDynamicSharedMemorySize,
                         TOP_SMEM);

    feat_kernel<<<SAMP_BLOCKS + 8, 256>>>(
        user, item, brand_idx, cat_idx, cat_len, text_idx, text_len,
        sales_rank, user_tab, item_tab, brand_tab, cat_tab, text_tab,
        W_bot, b_bot, W_proj, b_proj, W_t1, W_t2);

    top_mma<<<BB / MTILE, 512, TOP_SMEM>>>(
        b_t1, b_t2, W_t3, b_t3, out);
}

// round 17
// speedup vs baseline: 1.5387x; 1.0924x over previous
#include <cuda_runtime.h>
#include <cuda_bf16.h>
#include <cstdint>

#define BB 16384
#define DD 64
#define LCAT 8
#define LTXT 64
#define NTOPIN 79
#define NT1 128
#define NT2 64
#define SAMP_BLOCKS (BB / 8)
#define MTILE 64

typedef unsigned long long u64;

// Packed bf16 hi/lo x, transposed: g_xP[k][s], k in [0,80), zero-padded k=79
__device__ uint32_t g_xP[80 * BB];
// Pre-split weights (K-major rows: [j][k])
__device__ __align__(16) __nv_bfloat16 gW1hi[128 * 80];
__device__ __align__(16) __nv_bfloat16 gW1lo[128 * 80];
__device__ __align__(16) __nv_bfloat16 gW2hi[64 * 128];
__device__ __align__(16) __nv_bfloat16 gW2lo[64 * 128];

__device__ __forceinline__ uint32_t smem_u32(const void* p) {
    uint32_t a;
    asm("{ .reg .u64 t; cvta.to.shared.u64 t, %1; cvt.u32.u64 %0, t; }"
        : "=r"(a) : "l"(p));
    return a;
}
__device__ __forceinline__ void ldsm_x4(uint32_t addr, uint32_t* r) {
    asm volatile("ldmatrix.sync.aligned.m8n8.x4.shared.b16 {%0,%1,%2,%3}, [%4];"
        : "=r"(r[0]), "=r"(r[1]), "=r"(r[2]), "=r"(r[3]) : "r"(addr));
}
__device__ __forceinline__ void mma_bf16(float* d, const uint32_t* a,
                                         uint32_t b0, uint32_t b1) {
    asm volatile("mma.sync.aligned.m16n8k16.row.col.f32.bf16.bf16.f32 "
        "{%0,%1,%2,%3}, {%4,%5,%6,%7}, {%8,%9}, {%0,%1,%2,%3};"
        : "+f"(d[0]), "+f"(d[1]), "+f"(d[2]), "+f"(d[3])
        : "r"(a[0]), "r"(a[1]), "r"(a[2]), "r"(a[3]), "r"(b0), "r"(b1));
}
__device__ __forceinline__ void bsplit(float v, __nv_bfloat16& h, __nv_bfloat16& l) {
    h = __float2bfloat16(v);
    l = __float2bfloat16(v - __bfloat162float(h));
}
__device__ __forceinline__ void bsplit2(float v0, float v1,
                                        __nv_bfloat162& ph, __nv_bfloat162& pl) {
    __nv_bfloat16 h0, l0, h1, l1;
    bsplit(v0, h0, l0); bsplit(v1, h1, l1);
    ph.x = h0; ph.y = h1; pl.x = l0; pl.y = l1;
}
__device__ __forceinline__ uint32_t packv(float v) {
    __nv_bfloat16 h, l;
    bsplit(v, h, l);
    return ((uint32_t)__bfloat16_as_ushort(l) << 16) | __bfloat16_as_ushort(h);
}

// ---------------------------------------------------------------------------
// Kernel 1: warp-per-sample + embedded weight prepack (8 trailing blocks).
// IDENTICAL to R12/R16 (best measured feat).
// ---------------------------------------------------------------------------
__global__ __launch_bounds__(256, 4) void feat_kernel(
    const int* __restrict__ user, const int* __restrict__ item,
    const int* __restrict__ brand, const int* __restrict__ cat_idx,
    const int* __restrict__ cat_len, const int* __restrict__ text_idx,
    const int* __restrict__ text_len, const float* __restrict__ sales_rank,
    const float* __restrict__ user_tab, const float* __restrict__ item_tab,
    const float* __restrict__ brand_tab, const float* __restrict__ cat_tab,
    const float* __restrict__ text_tab,
    const float* __restrict__ W_bot, const float* __restrict__ b_bot,
    const float* __restrict__ W_proj, const float* __restrict__ b_proj,
    const float* __restrict__ W1,    const float* __restrict__ W2)
{
    const unsigned FULL = 0xFFFFFFFFu;

    if (blockIdx.x >= SAMP_BLOCKS) {
        int tid = (blockIdx.x - SAMP_BLOCKS) * 256 + threadIdx.x;
        for (int idx = tid; idx < 128 * 80; idx += 2048) {
            int j = idx / 80, k = idx % 80;
            float v = (k < NTOPIN) ? W1[k * 128 + j] : 0.f;
            __nv_bfloat16 h, l; bsplit(v, h, l);
            gW1hi[idx] = h; gW1lo[idx] = l;
        }
        for (int idx = tid; idx < 64 * 128; idx += 2048) {
            int m = idx >> 7, k = idx & 127;
            float v = W2[k * 64 + m];
            __nv_bfloat16 h, l; bsplit(v, h, l);
            gW2hi[idx] = h; gW2lo[idx] = l;
        }
        return;
    }

    int gwarp = (blockIdx.x * blockDim.x + threadIdx.x) >> 5;
    int lane  = threadIdx.x & 31;
    const int s = gwarp;

    const float2* ut = (const float2*)user_tab;
    const float2* it = (const float2*)item_tab;
    const float2* bt = (const float2*)brand_tab;
    const float4* ct4 = (const float4*)cat_tab;
    const float4* tt4 = (const float4*)text_tab;

    const int sub = lane >> 4;
    const int q   = lane & 15;

    int ui = user[s];
    int ii = item[s];
    int bi = brand[s];
    float2 fu = __ldcs(ut + (size_t)ui * 32 + lane);
    float2 fi = __ldcs(it + (size_t)ii * 32 + lane);
    float2 fb = bt[(size_t)bi * 32 + lane];

    int clen = cat_len[s];
    int tlen = text_len[s];
    int creg = (lane < LCAT) ? cat_idx[s * LCAT + lane] : 0;
    int t0 = text_idx[s * LTXT + lane];
    int t1 = text_idx[s * LTXT + 32 + lane];

    float4 cacc = make_float4(0.f, 0.f, 0.f, 0.f);
    #pragma unroll
    for (int i = 0; i < LCAT; i += 2) {
        int r = i + sub;
        int idx = __shfl_sync(FULL, creg, r);
        if (r < clen) {
            float4 v = ct4[(size_t)idx * 16 + q];
            cacc.x += v.x; cacc.y += v.y; cacc.z += v.z; cacc.w += v.w;
        }
    }

    float4 tacc = make_float4(0.f, 0.f, 0.f, 0.f);
    #pragma unroll
    for (int g = 0; g < 4; g++) {
        float4 v[8];
        #pragma unroll
        for (int j = 0; j < 8; j++) {
            int i = g * 16 + 2 * j;
            int r = i + sub;
            int idx = __shfl_sync(FULL, (i < 32) ? t0 : t1, r & 31);
            v[j] = make_float4(0.f, 0.f, 0.f, 0.f);
            if (r < tlen) v[j] = __ldcs(tt4 + (size_t)idx * 16 + q);
        }
        float4 p0, p1;
        p0.x = v[0].x + v[1].x; p0.y = v[0].y + v[1].y;
        p0.z = v[0].z + v[1].z; p0.w = v[0].w + v[1].w;
        p1.x = v[2].x + v[3].x; p1.y = v[2].y + v[3].y;
        p1.z = v[2].z + v[3].z; p1.w = v[2].w + v[3].w;
        p0.x += v[4].x + v[5].x; p0.y += v[4].y + v[5].y;
        p0.z += v[4].z + v[5].z; p0.w += v[4].w + v[5].w;
        p1.x += v[6].x + v[7].x; p1.y += v[6].y + v[7].y;
        p1.z += v[6].z + v[7].z; p1.w += v[6].w + v[7].w;
        tacc.x += p0.x + p1.x; tacc.y += p0.y + p1.y;
        tacc.z += p0.z + p1.z; tacc.w += p0.w + p1.w;
    }

    {
        float cinv = 1.f / (float)max(clen, 1);
        float tinv = 1.f / (float)max(tlen, 1);
        cacc.x = (cacc.x + __shfl_down_sync(FULL, cacc.x, 16)) * cinv;
        cacc.y = (cacc.y + __shfl_down_sync(FULL, cacc.y, 16)) * cinv;
        cacc.z = (cacc.z + __shfl_down_sync(FULL, cacc.z, 16)) * cinv;
        cacc.w = (cacc.w + __shfl_down_sync(FULL, cacc.w, 16)) * cinv;
        tacc.x = (tacc.x + __shfl_down_sync(FULL, tacc.x, 16)) * tinv;
        tacc.y = (tacc.y + __shfl_down_sync(FULL, tacc.y, 16)) * tinv;
        tacc.z = (tacc.z + __shfl_down_sync(FULL, tacc.z, 16)) * tinv;
        tacc.w = (tacc.w + __shfl_down_sync(FULL, tacc.w, 16)) * tinv;
    }

    float2 cv, tv;
    {
        int src = lane >> 1;
        float cx = __shfl_sync(FULL, cacc.x, src);
        float cy = __shfl_sync(FULL, cacc.y, src);
        float cz = __shfl_sync(FULL, cacc.z, src);
        float cw = __shfl_sync(FULL, cacc.w, src);
        float tx = __shfl_sync(FULL, tacc.x, src);
        float ty = __shfl_sync(FULL, tacc.y, src);
        float tz = __shfl_sync(FULL, tacc.z, src);
        float tw = __shfl_sync(FULL, tacc.w, src);
        if (lane & 1) { cv = make_float2(cz, cw); tv = make_float2(tz, tw); }
        else          { cv = make_float2(cx, cy); tv = make_float2(tx, ty); }
    }

    float sr = sales_rank[s];
    float d0 = fmaxf(fmaf(sr, W_bot[2 * lane],     b_bot[2 * lane]),     0.f);
    float d1 = fmaxf(fmaf(sr, W_bot[2 * lane + 1], b_bot[2 * lane + 1]), 0.f);

    const float2* wp = (const float2*)W_proj;
    float2 du = make_float2(b_proj[2 * lane], b_proj[2 * lane + 1]);
    #pragma unroll
    for (int k = 0; k < DD; k++) {
        float dk = __shfl_sync(FULL, (k & 1) ? d1 : d0, k >> 1);
        float2 w = wp[k * 32 + lane];
        du.x = fmaf(dk, w.x, du.x);
        du.y = fmaf(dk, w.y, du.y);
    }

    float2 f[6];
    f[0] = fu; f[1] = fi; f[2] = fb; f[3] = cv; f[4] = tv; f[5] = du;

    float keep = 0.f;
    int p = 0;
    #pragma unroll
    for (int a = 0; a < 6; a++) {
        #pragma unroll
        for (int b = a + 1; b < 6; b++) {
            float dv = f[a].x * f[b].x + f[a].y * f[b].y;
            #pragma unroll
            for (int o = 16; o > 0; o >>= 1)
                dv += __shfl_xor_sync(FULL, dv, o);
            if (lane == p) keep = dv;
            p++;
        }
    }

    if (lane < 15) g_xP[lane * BB + s] = packv(keep);
    g_xP[(15 + 2 * lane) * BB + s] = packv(d0);
    g_xP[(16 + 2 * lane) * BB + s] = packv(d1);
    if (lane == 31) g_xP[79 * BB + s] = 0u;
}

// ---------------------------------------------------------------------------
// Kernel 2: top MLP. R16 layout; mainloops restructured to hoist fragments
// across split-terms: per k-step load aH,aL,bH,bL ONCE, issue all 3 terms.
// 33% fewer ldmatrix -> lower smem crossbar pressure, shorter chain.
// ---------------------------------------------------------------------------
#define ASTR   176
#define H1STR  272
#define B1STR  176
#define W2STR  272

#define OFF_AHI   0
#define OFF_ALO   (OFF_AHI + MTILE * ASTR)
#define OFF_B1HI  (OFF_ALO + MTILE * ASTR)
#define OFF_B1LO  (OFF_B1HI + 128 * B1STR)
#define OFF_H1HI  OFF_B1HI
#define OFF_H1LO  OFF_B1LO
#define OFF_W2HI  (OFF_B1LO + 128 * B1STR)
#define OFF_W2LO  (OFF_W2HI + 64 * W2STR)
#define OFF_SB1   (OFF_W2LO + 64 * W2STR)
#define OFF_SB2   (OFF_SB1 + 512)
#define OFF_SW3   (OFF_SB2 + 256)
#define OFF_SB3   (OFF_SW3 + 256)
#define OFF_SPZ   (OFF_SB3 + 16)
#define TOP_SMEM  (OFF_SPZ + 4 * 64 * 4)

__global__ __launch_bounds__(512, 2) void top_mma(
    const float* __restrict__ b1, const float* __restrict__ b2,
    const float* __restrict__ W3, const float* __restrict__ b3,
    float* __restrict__ out)
{
    extern __shared__ __align__(16) char sm[];
    const uint32_t smb = smem_u32(sm);
    const int tid = threadIdx.x;
    const int wid = tid >> 5;
    const int lane = tid & 31;
    const int S0 = blockIdx.x * MTILE;
    const unsigned FULL = 0xFFFFFFFFu;

    float* sb1 = (float*)(sm + OFF_SB1);
    float* sb2 = (float*)(sm + OFF_SB2);
    float* sW3 = (float*)(sm + OFF_SW3);
    float* sb3 = (float*)(sm + OFF_SB3);
    float* sPz = (float*)(sm + OFF_SPZ);

    // ---- phase 0: ALL global staging up-front ----
    #pragma unroll
    for (int it = 0; it < 5; it++) {
        int idx = tid + it * 512;
        int row = idx & 63, k0 = (idx >> 6) * 2;
        uint32_t p0 = g_xP[(size_t)k0 * BB + S0 + row];
        uint32_t p1 = g_xP[(size_t)(k0 + 1) * BB + S0 + row];
        uint32_t hp = __byte_perm(p0, p1, 0x5410);
        uint32_t lp = __byte_perm(p0, p1, 0x7632);
        *(uint32_t*)(sm + OFF_AHI + row * ASTR + k0 * 2) = hp;
        *(uint32_t*)(sm + OFF_ALO + row * ASTR + k0 * 2) = lp;
    }
    for (int idx = tid; idx < 1280; idx += 512) {
        int r = idx / 10, c = idx % 10;
        *(uint4*)(sm + OFF_B1HI + r * B1STR + c * 16) =
            *(const uint4*)(gW1hi + r * 80 + c * 8);
        *(uint4*)(sm + OFF_B1LO + r * B1STR + c * 16) =
            *(const uint4*)(gW1lo + r * 80 + c * 8);
    }
    #pragma unroll
    for (int it = 0; it < 2; it++) {
        int idx = tid + it * 512;
        int r = idx >> 4, c = idx & 15;
        *(uint4*)(sm + OFF_W2HI + r * W2STR + c * 16) =
            *(const uint4*)(gW2hi + r * 128 + c * 8);
        *(uint4*)(sm + OFF_W2LO + r * W2STR + c * 16) =
            *(const uint4*)(gW2lo + r * 128 + c * 8);
    }
    if (tid < 128) sb1[tid] = b1[tid];
    if (tid < 64) { sb2[tid] = b2[tid]; sW3[tid] = W3[tid]; }
    if (tid == 0) sb3[0] = b3[0];
    __syncthreads();

    // ================= layer 1 (D1 = 64x128) =================
    const int mt  = wid >> 2;
    const int ntb = (wid & 3) * 32;
    float acc[4][4];
    #pragma unroll
    for (int i = 0; i < 4; i++)
        #pragma unroll
        for (int j = 0; j < 4; j++) acc[i][j] = 0.f;

    const uint32_t a1_off = (mt * 16 + (lane & 15)) * ASTR + ((lane >> 4) * 8) * 2;
    const uint32_t a2_off = (mt * 16 + (lane & 15)) * H1STR + ((lane >> 4) * 8) * 2;
    const uint32_t b_row = (lane & 7) + ((lane >> 4) & 1) * 8;
    const uint32_t b_k8  = ((lane >> 3) & 1) * 8;

    #pragma unroll
    for (int ks = 0; ks < 5; ks++) {
        int k0 = ks * 16;
        uint32_t aH[4], aL[4];
        ldsm_x4(smb + OFF_AHI + a1_off + k0 * 2, aH);
        ldsm_x4(smb + OFF_ALO + a1_off + k0 * 2, aL);
        #pragma unroll
        for (int half = 0; half < 2; half++) {
            int n0h = ntb + half * 16;
            uint32_t bofs = (n0h + b_row) * B1STR + (k0 + b_k8) * 2;
            uint32_t bH[4], bL[4];
            ldsm_x4(smb + OFF_B1HI + bofs, bH);
            ldsm_x4(smb + OFF_B1LO + bofs, bL);
            mma_bf16(acc[half * 2],     aH, bH[0], bH[1]);
            mma_bf16(acc[half * 2 + 1], aH, bH[2], bH[3]);
            mma_bf16(acc[half * 2],     aH, bL[0], bL[1]);
            mma_bf16(acc[half * 2 + 1], aH, bL[2], bL[3]);
            mma_bf16(acc[half * 2],     aL, bH[0], bH[1]);
            mma_bf16(acc[half * 2 + 1], aL, bH[2], bH[3]);
        }
    }
    __syncthreads();   // everyone done reading B1 before h1 overlays it

    // ---- epilogue 1: h1 = relu(D1 + b1) -> H1 region (overlays B1) ----
    {
        int r0 = mt * 16 + (lane >> 2);
        #pragma unroll
        for (int nt = 0; nt < 4; nt++) {
            int c = ntb + nt * 8 + 2 * (lane & 3);
            float h0a = fmaxf(acc[nt][0] + sb1[c],     0.f);
            float h1a = fmaxf(acc[nt][1] + sb1[c + 1], 0.f);
            float h0b = fmaxf(acc[nt][2] + sb1[c],     0.f);
            float h1b = fmaxf(acc[nt][3] + sb1[c + 1], 0.f);
            __nv_bfloat162 ph, pl;
            bsplit2(h0a, h1a, ph, pl);
            *(__nv_bfloat162*)(sm + OFF_H1HI + r0 * H1STR + c * 2) = ph;
            *(__nv_bfloat162*)(sm + OFF_H1LO + r0 * H1STR + c * 2) = pl;
            bsplit2(h0b, h1b, ph, pl);
            *(__nv_bfloat162*)(sm + OFF_H1HI + (r0 + 8) * H1STR + c * 2) = ph;
            *(__nv_bfloat162*)(sm + OFF_H1LO + (r0 + 8) * H1STR + c * 2) = pl;
        }
    }
    __syncthreads();

    // ================= layer 2 (D2 = 64x64) =================
    const int n0 = (wid & 3) * 16;
    float acc2[2][4];
    #pragma unroll
    for (int i = 0; i < 2; i++)
        #pragma unroll
        for (int j = 0; j < 4; j++) acc2[i][j] = 0.f;

    #pragma unroll
    for (int ks = 0; ks < 8; ks++) {
        int k0 = ks * 16;
        uint32_t aH[4], aL[4], bH[4], bL[4];
        ldsm_x4(smb + OFF_H1HI + a2_off + k0 * 2, aH);
        ldsm_x4(smb + OFF_H1LO + a2_off + k0 * 2, aL);
        uint32_t bofs = (n0 + b_row) * W2STR + (k0 + b_k8) * 2;
        ldsm_x4(smb + OFF_W2HI + bofs, bH);
        ldsm_x4(smb + OFF_W2LO + bofs, bL);
        mma_bf16(acc2[0], aH, bH[0], bH[1]);
        mma_bf16(acc2[1], aH, bH[2], bH[3]);
        mma_bf16(acc2[0], aH, bL[0], bL[1]);
        mma_bf16(acc2[1], aH, bL[2], bL[3]);
        mma_bf16(acc2[0], aL, bH[0], bH[1]);
        mma_bf16(acc2[1], aL, bH[2], bH[3]);
    }

    // ---- layer-3 partials + reduction + sigmoid ----
    {
        float z0 = 0.f, z1 = 0.f;
        #pragma unroll
        for (int nt = 0; nt < 2; nt++) {
            int c = n0 + nt * 8 + 2 * (lane & 3);
            float w0 = sW3[c], w1 = sW3[c + 1];
            z0 = fmaf(fmaxf(acc2[nt][0] + sb2[c],     0.f), w0, z0);
            z0 = fmaf(fmaxf(acc2[nt][1] + sb2[c + 1], 0.f), w1, z0);
            z1 = fmaf(fmaxf(acc2[nt][2] + sb2[c],     0.f), w0, z1);
            z1 = fmaf(fmaxf(acc2[nt][3] + sb2[c + 1], 0.f), w1, z1);
        }
        z0 += __shfl_xor_sync(FULL, z0, 1);
        z0 += __shfl_xor_sync(FULL, z0, 2);
        z1 += __shfl_xor_sync(FULL, z1, 1);
        z1 += __shfl_xor_sync(FULL, z1, 2);
        if ((lane & 3) == 0) {
            int r0 = mt * 16 + (lane >> 2);
            int ng = wid & 3;
            sPz[ng * 64 + r0]     = z0;
            sPz[ng * 64 + r0 + 8] = z1;
        }
    }
    __syncthreads();

    if (tid < 64) {
        float z = sb3[0] + sPz[tid] + sPz[64 + tid] + sPz[128 + tid] + sPz[192 + tid];
        out[S0 + tid] = 1.f / (1.f + __expf(-z));
    }
}

// ---------------------------------------------------------------------------
extern "C" void kernel_launch(void* const* d_in, const int* in_sizes, int n_in,
                              void* d_out, int out_size)
{
    const int*   user       = (const int*)  d_in[0];
    const int*   item       = (const int*)  d_in[1];
    const int*   brand_idx  = (const int*)  d_in[2];
    const int*   cat_idx    = (const int*)  d_in[3];
    const int*   cat_len    = (const int*)  d_in[4];
    const int*   text_idx   = (const int*)  d_in[5];
    const int*   text_len   = (const int*)  d_in[6];
    const float* sales_rank = (const float*)d_in[7];
    const float* user_tab   = (const float*)d_in[8];
    const float* item_tab   = (const float*)d_in[9];
    const float* brand_tab  = (const float*)d_in[10];
    const float* cat_tab    = (const float*)d_in[11];
    const float* text_tab   = (const float*)d_in[12];
    const float* W_bot      = (const float*)d_in[13];
    const float* b_bot      = (const float*)d_in[14];
    const float* W_proj     = (const float*)d_in[15];
    const float* b_proj     = (const float*)d_in[16];
    const float* W_t1       = (const float*)d_in[17];
    const float* b_t1       = (const float*)d_in[18];
    const float* W_t2       = (const float*)d_in[19];
    const float* b_t2       = (const float*)d_in[20];
    const float* W_t3       = (const float*)d_in[21];
    const float* b_t3       = (const float*)d_in[22];
    float* out = (float*)d_out;

    cudaFuncSetAttribute(top_mma,
                         cudaFuncAttributeMaxDynamicSharedMemorySize,
                         TOP_SMEM);

    feat_kernel<<<SAMP_BLOCKS + 8, 256>>>(
        user, item, brand_idx, cat_idx, cat_len, text_idx, text_len,
        sales_rank, user_tab, item_tab, brand_tab, cat_tab, text_tab,
        W_bot, b_bot, W_proj, b_proj, W_t1, W_t2);

    top_mma<<<BB / MTILE, 512, TOP_SMEM>>>(
        b_t1, b_t2, W_t3, b_t3, out);
}